// round 1
// baseline (speedup 1.0000x reference)
#include <cuda_runtime.h>
#include <math.h>

#define BATCH  256
#define SEQ    256
#define IN_DIM 128
#define HID    1024
#define NOUT   10

// Scratch: xproj laid out [t][b][h] so each step reads a contiguous 1MB slice.
__device__ float g_xproj[(size_t)SEQ * BATCH * HID];   // 256 MB
__device__ float g_h[2][BATCH * HID];                  // ping-pong hidden state

// ---------------------------------------------------------------------------
// Kernel 1: xproj[s][b][h] = sum_i x[b][s][i] * Whx[i][h] + bh[h]
// M = BATCH*SEQ = 65536 (rows m = b*SEQ + s), N = 1024, K = 128.
// BM=64, BN=64, BK=16, 256 threads, 4x4 micro-tile.
// ---------------------------------------------------------------------------
__global__ __launch_bounds__(256) void xproj_kernel(
    const float* __restrict__ x, const float* __restrict__ Whx,
    const float* __restrict__ bh)
{
    const int n0 = blockIdx.x * 64;
    const int m0 = blockIdx.y * 64;
    __shared__ float As[64][20];   // padded: read-broadcast conflict-free
    __shared__ float Bs[16][64];
    const int t  = threadIdx.x;
    const int tx = t & 15;         // n-group
    const int ty = t >> 4;         // m-group
    float acc[4][4] = {};

    for (int k0 = 0; k0 < IN_DIM; k0 += 16) {
        {   // A tile 64x16: one float4 per thread, coalesced
            int m = t >> 2;
            int k = (t & 3) * 4;
            float4 v = *reinterpret_cast<const float4*>(&x[(size_t)(m0 + m) * IN_DIM + k0 + k]);
            *reinterpret_cast<float4*>(&As[m][k]) = v;
        }
        {   // B tile 16x64: one float4 per thread, coalesced
            int k = t >> 4;
            int n = (t & 15) * 4;
            float4 v = *reinterpret_cast<const float4*>(&Whx[(size_t)(k0 + k) * HID + n0 + n]);
            *reinterpret_cast<float4*>(&Bs[k][n]) = v;
        }
        __syncthreads();
        #pragma unroll
        for (int k = 0; k < 16; k++) {
            float a[4];
            #pragma unroll
            for (int i = 0; i < 4; i++) a[i] = As[ty * 4 + i][k];
            float4 bv = *reinterpret_cast<const float4*>(&Bs[k][tx * 4]);
            float b[4] = {bv.x, bv.y, bv.z, bv.w};
            #pragma unroll
            for (int i = 0; i < 4; i++)
                #pragma unroll
                for (int j = 0; j < 4; j++)
                    acc[i][j] += a[i] * b[j];
        }
        __syncthreads();
    }

    float4 bias = *reinterpret_cast<const float4*>(&bh[n0 + tx * 4]);
    #pragma unroll
    for (int i = 0; i < 4; i++) {
        int m  = m0 + ty * 4 + i;
        int b_ = m >> 8;     // / SEQ
        int s  = m & 255;    // % SEQ
        float4 o;
        o.x = acc[i][0] + bias.x;
        o.y = acc[i][1] + bias.y;
        o.z = acc[i][2] + bias.z;
        o.w = acc[i][3] + bias.w;
        *reinterpret_cast<float4*>(
            &g_xproj[(size_t)s * BATCH * HID + (size_t)b_ * HID + n0 + tx * 4]) = o;
    }
}

// ---------------------------------------------------------------------------
// Kernel 2: step t (t >= 1): h_next = tanh(xproj_t + h_prev @ Whh)
// M=256 (batch), N=1024, K=1024. BM=32, BN=64, BK=32, 256 threads, 4x2 tile.
// Grid = 16 x 8 = 128 CTAs (~1 per SM).
// ---------------------------------------------------------------------------
__global__ __launch_bounds__(256) void step_kernel(
    const float* __restrict__ Whh, int t)
{
    const float* __restrict__ hprev = g_h[(t - 1) & 1];
    float* __restrict__ hnext       = g_h[t & 1];
    const float* __restrict__ xp    = &g_xproj[(size_t)t * BATCH * HID];

    const int n0 = blockIdx.x * 64;
    const int b0 = blockIdx.y * 32;
    __shared__ float As[32][32];
    __shared__ float Bs[32][64];
    const int tid = threadIdx.x;
    const int tx = tid & 31;   // n-group (TN=2)
    const int ty = tid >> 5;   // m-group (TM=4), warp-uniform -> As reads broadcast
    float acc[4][2] = {};

    for (int k0 = 0; k0 < HID; k0 += 32) {
        {   // A tile 32x32: float4 per thread, coalesced (8 threads/row)
            int m = tid >> 3;
            int k = (tid & 7) * 4;
            *reinterpret_cast<float4*>(&As[m][k]) =
                *reinterpret_cast<const float4*>(&hprev[(size_t)(b0 + m) * HID + k0 + k]);
        }
        #pragma unroll
        for (int i = 0; i < 2; i++) {  // B tile 32x64: 2 float4 per thread
            int idx = tid + i * 256;
            int k   = idx >> 4;
            int n4  = (idx & 15) * 4;
            *reinterpret_cast<float4*>(&Bs[k][n4]) =
                *reinterpret_cast<const float4*>(&Whh[(size_t)(k0 + k) * HID + n0 + n4]);
        }
        __syncthreads();
        #pragma unroll
        for (int k = 0; k < 32; k++) {
            float a[4];
            #pragma unroll
            for (int i = 0; i < 4; i++) a[i] = As[ty * 4 + i][k];
            float2 bv = *reinterpret_cast<const float2*>(&Bs[k][tx * 2]);
            #pragma unroll
            for (int i = 0; i < 4; i++) {
                acc[i][0] += a[i] * bv.x;
                acc[i][1] += a[i] * bv.y;
            }
        }
        __syncthreads();
    }

    #pragma unroll
    for (int i = 0; i < 4; i++) {
        int b = b0 + ty * 4 + i;
        int n = n0 + tx * 2;
        float2 xv = *reinterpret_cast<const float2*>(&xp[(size_t)b * HID + n]);
        float2 o;
        o.x = tanhf(acc[i][0] + xv.x);
        o.y = tanhf(acc[i][1] + xv.y);
        *reinterpret_cast<float2*>(&hnext[(size_t)b * HID + n]) = o;
    }
}

// ---------------------------------------------------------------------------
// Kernel: step 0 — h = tanh(xproj_0)  (h_prev = 0)
// ---------------------------------------------------------------------------
__global__ void step0_kernel()
{
    int i = blockIdx.x * blockDim.x + threadIdx.x;
    g_h[0][i] = tanhf(g_xproj[i]);
}

// ---------------------------------------------------------------------------
// Kernel 3: logits = h_final @ Why + bo; softmax over 10. One warp per batch.
// ---------------------------------------------------------------------------
__global__ void out_kernel(const float* __restrict__ Why,
                           const float* __restrict__ bo,
                           float* __restrict__ out)
{
    const int b    = blockIdx.x;
    const int lane = threadIdx.x;  // 32 threads
    const float* __restrict__ h = g_h[(SEQ - 1) & 1];

    float acc[NOUT] = {};
    for (int k = lane; k < HID; k += 32) {
        float hv = h[(size_t)b * HID + k];
        #pragma unroll
        for (int o = 0; o < NOUT; o++)
            acc[o] += hv * Why[k * NOUT + o];
    }
    #pragma unroll
    for (int o = 0; o < NOUT; o++) {
        #pragma unroll
        for (int s = 16; s; s >>= 1)
            acc[o] += __shfl_xor_sync(0xffffffffu, acc[o], s);
        acc[o] += bo[o];
    }
    if (lane == 0) {
        float mx = acc[0];
        #pragma unroll
        for (int o = 1; o < NOUT; o++) mx = fmaxf(mx, acc[o]);
        float sum = 0.f;
        float e[NOUT];
        #pragma unroll
        for (int o = 0; o < NOUT; o++) { e[o] = expf(acc[o] - mx); sum += e[o]; }
        float inv = 1.0f / sum;
        #pragma unroll
        for (int o = 0; o < NOUT; o++) out[b * NOUT + o] = e[o] * inv;
    }
}

// ---------------------------------------------------------------------------
extern "C" void kernel_launch(void* const* d_in, const int* in_sizes, int n_in,
                              void* d_out, int out_size)
{
    const float* x   = (const float*)d_in[0];
    const float* Whx = (const float*)d_in[1];
    const float* Whh = (const float*)d_in[2];
    const float* bh  = (const float*)d_in[3];
    const float* Why = (const float*)d_in[4];
    const float* bo  = (const float*)d_in[5];
    float* out = (float*)d_out;

    dim3 g1(HID / 64, (BATCH * SEQ) / 64);
    xproj_kernel<<<g1, 256>>>(x, Whx, bh);

    step0_kernel<<<(BATCH * HID) / 1024, 1024>>>();

    dim3 g2(HID / 64, BATCH / 32);
    for (int t = 1; t < SEQ; t++)
        step_kernel<<<g2, 256>>>(Whh, t);

    out_kernel<<<BATCH, 32>>>(Why, bo, out);
}

// round 5
// speedup vs baseline: 1.8972x; 1.8972x over previous
#include <cuda_runtime.h>
#include <cuda_bf16.h>
#include <math.h>

#define BATCH  256
#define SEQ    256
#define IN_DIM 128
#define HID    1024
#define NOUT   10

// ---------------------------------------------------------------------------
// Global scratch
// ---------------------------------------------------------------------------
__device__ float g_xproj[(size_t)SEQ * BATCH * HID];                 // [t][b][h]
__device__ __align__(16) __nv_bfloat16 g_Ahi[2][BATCH * HID];        // h split hi (ping-pong)
__device__ __align__(16) __nv_bfloat16 g_Alo[2][BATCH * HID];        // h split lo
__device__ __align__(16) __nv_bfloat16 g_BThi[HID * HID];            // Whh^T hi: [n][k]
__device__ __align__(16) __nv_bfloat16 g_BTlo[HID * HID];            // Whh^T lo: [n][k]

// ---------------------------------------------------------------------------
// cp.async helpers
// ---------------------------------------------------------------------------
__device__ __forceinline__ void cp_async16(void* smem_dst, const void* gmem_src) {
    unsigned sa = (unsigned)__cvta_generic_to_shared(smem_dst);
    asm volatile("cp.async.cg.shared.global [%0], [%1], 16;\n" :: "r"(sa), "l"(gmem_src));
}
__device__ __forceinline__ void cp_commit() { asm volatile("cp.async.commit_group;\n"); }
template <int N>
__device__ __forceinline__ void cp_wait() { asm volatile("cp.async.wait_group %0;\n" :: "n"(N)); }

// ---------------------------------------------------------------------------
// Prep: split Whh (fp32 [k][n]) into transposed bf16 hi/lo [n][k]
// ---------------------------------------------------------------------------
__global__ __launch_bounds__(256) void split_whh_kernel(const float* __restrict__ W)
{
    __shared__ float tile[32][33];
    const int n0 = blockIdx.x * 32;
    const int k0 = blockIdx.y * 32;
    const int tx = threadIdx.x;       // 0..31
    const int ty = threadIdx.y;       // 0..7
    #pragma unroll
    for (int i = 0; i < 4; i++)
        tile[ty + i * 8][tx] = W[(size_t)(k0 + ty + i * 8) * HID + n0 + tx];
    __syncthreads();
    #pragma unroll
    for (int i = 0; i < 4; i++) {
        int n = n0 + ty + i * 8;
        int k = k0 + tx;
        float w = tile[tx][ty + i * 8];
        __nv_bfloat16 hi = __float2bfloat16(w);
        __nv_bfloat16 lo = __float2bfloat16(w - __bfloat162float(hi));
        g_BThi[(size_t)n * HID + k] = hi;
        g_BTlo[(size_t)n * HID + k] = lo;
    }
}

// ---------------------------------------------------------------------------
// Kernel 1: xproj[s][b][h] = x[b][s][:] @ Whx + bh   (fp32 SIMT, unchanged)
// ---------------------------------------------------------------------------
__global__ __launch_bounds__(256) void xproj_kernel(
    const float* __restrict__ x, const float* __restrict__ Whx,
    const float* __restrict__ bh)
{
    const int n0 = blockIdx.x * 64;
    const int m0 = blockIdx.y * 64;
    __shared__ float As[64][20];
    __shared__ float Bs[16][64];
    const int t  = threadIdx.x;
    const int tx = t & 15;
    const int ty = t >> 4;
    float acc[4][4] = {};

    for (int k0 = 0; k0 < IN_DIM; k0 += 16) {
        {
            int m = t >> 2;
            int k = (t & 3) * 4;
            float4 v = *reinterpret_cast<const float4*>(&x[(size_t)(m0 + m) * IN_DIM + k0 + k]);
            *reinterpret_cast<float4*>(&As[m][k]) = v;
        }
        {
            int k = t >> 4;
            int n = (t & 15) * 4;
            float4 v = *reinterpret_cast<const float4*>(&Whx[(size_t)(k0 + k) * HID + n0 + n]);
            *reinterpret_cast<float4*>(&Bs[k][n]) = v;
        }
        __syncthreads();
        #pragma unroll
        for (int k = 0; k < 16; k++) {
            float a[4];
            #pragma unroll
            for (int i = 0; i < 4; i++) a[i] = As[ty * 4 + i][k];
            float4 bv = *reinterpret_cast<const float4*>(&Bs[k][tx * 4]);
            float b[4] = {bv.x, bv.y, bv.z, bv.w};
            #pragma unroll
            for (int i = 0; i < 4; i++)
                #pragma unroll
                for (int j = 0; j < 4; j++)
                    acc[i][j] += a[i] * b[j];
        }
        __syncthreads();
    }

    float4 bias = *reinterpret_cast<const float4*>(&bh[n0 + tx * 4]);
    #pragma unroll
    for (int i = 0; i < 4; i++) {
        int m  = m0 + ty * 4 + i;
        int b_ = m >> 8;
        int s  = m & 255;
        float4 o;
        o.x = acc[i][0] + bias.x;
        o.y = acc[i][1] + bias.y;
        o.z = acc[i][2] + bias.z;
        o.w = acc[i][3] + bias.w;
        *reinterpret_cast<float4*>(
            &g_xproj[(size_t)s * BATCH * HID + (size_t)b_ * HID + n0 + tx * 4]) = o;
    }
}

// ---------------------------------------------------------------------------
// Step 0: h = tanh(xproj_0), split to bf16 hi/lo in buffer 0
// ---------------------------------------------------------------------------
__global__ void step0_kernel()
{
    int i = blockIdx.x * blockDim.x + threadIdx.x;
    float h = tanhf(g_xproj[i]);
    __nv_bfloat16 hi = __float2bfloat16(h);
    __nv_bfloat16 lo = __float2bfloat16(h - __bfloat162float(hi));
    g_Ahi[0][i] = hi;
    g_Alo[0][i] = lo;
}

// ---------------------------------------------------------------------------
// Step kernel (t >= 1): h_t = tanh(xp_t + h_{t-1} @ Whh)
//   bf16 tensor-core MMA with 2-term error split (3 passes, fp32 accum).
//   CTA: 32(M) x 64(N), 4 warps (2x2 of 16x32 warp tiles), K pipelined BK=32.
//   Grid: 16 x 8 = 128 CTAs.
// ---------------------------------------------------------------------------
#define BK   32
#define SA   40           // padded row stride (bf16 elems) -> 80B, conflict-free
#define NK   (HID / BK)   // 32

__global__ __launch_bounds__(128) void step_kernel(int t)
{
    const __nv_bfloat16* __restrict__ Ahi_r = g_Ahi[(t - 1) & 1];
    const __nv_bfloat16* __restrict__ Alo_r = g_Alo[(t - 1) & 1];
    __nv_bfloat16* __restrict__ Ahi_w = g_Ahi[t & 1];
    __nv_bfloat16* __restrict__ Alo_w = g_Alo[t & 1];
    const float* __restrict__ xp = &g_xproj[(size_t)t * BATCH * HID];

    const int n0 = blockIdx.x * 64;
    const int m0 = blockIdx.y * 32;

    __shared__ __align__(16) __nv_bfloat16 sAhi[2][32][SA];
    __shared__ __align__(16) __nv_bfloat16 sAlo[2][32][SA];
    __shared__ __align__(16) __nv_bfloat16 sBhi[2][64][SA];
    __shared__ __align__(16) __nv_bfloat16 sBlo[2][64][SA];

    const int tid  = threadIdx.x;
    const int lane = tid & 31;
    const int wid  = tid >> 5;         // 0..3
    const int wm   = wid & 1;          // warp M group (16 rows)
    const int wn   = wid >> 1;         // warp N group (32 cols)
    const int g    = lane >> 2;        // 0..7
    const int t2   = (lane & 3) * 2;   // 0,2,4,6

    // staging indices (per thread, per 16B chunk)
    const int am = tid >> 2;           // 0..31  A row
    const int ch = tid & 3;            // 0..3   16B chunk within 64B row-chunk

    float c[4][4];                     // [ntile][c0..c3]
    #pragma unroll
    for (int i = 0; i < 4; i++)
        #pragma unroll
        for (int j = 0; j < 4; j++) c[i][j] = 0.f;

    // ---- prologue: stage k-chunk 0 into buffer 0
    {
        const int k0 = 0;
        cp_async16(&sAhi[0][am][ch * 8], &Ahi_r[(size_t)(m0 + am) * HID + k0 + ch * 8]);
        cp_async16(&sAlo[0][am][ch * 8], &Alo_r[(size_t)(m0 + am) * HID + k0 + ch * 8]);
        #pragma unroll
        for (int i = 0; i < 2; i++) {
            int bn = (tid + i * 128) >> 2;     // 0..63
            cp_async16(&sBhi[0][bn][ch * 8], &g_BThi[(size_t)(n0 + bn) * HID + k0 + ch * 8]);
            cp_async16(&sBlo[0][bn][ch * 8], &g_BTlo[(size_t)(n0 + bn) * HID + k0 + ch * 8]);
        }
        cp_commit();
    }

    #pragma unroll 2
    for (int kt = 0; kt < NK; kt++) {
        const int sb = kt & 1;
        if (kt + 1 < NK) {
            const int k0 = (kt + 1) * BK;
            const int nb = (kt + 1) & 1;
            cp_async16(&sAhi[nb][am][ch * 8], &Ahi_r[(size_t)(m0 + am) * HID + k0 + ch * 8]);
            cp_async16(&sAlo[nb][am][ch * 8], &Alo_r[(size_t)(m0 + am) * HID + k0 + ch * 8]);
            #pragma unroll
            for (int i = 0; i < 2; i++) {
                int bn = (tid + i * 128) >> 2;
                cp_async16(&sBhi[nb][bn][ch * 8], &g_BThi[(size_t)(n0 + bn) * HID + k0 + ch * 8]);
                cp_async16(&sBlo[nb][bn][ch * 8], &g_BTlo[(size_t)(n0 + bn) * HID + k0 + ch * 8]);
            }
            cp_commit();
            cp_wait<1>();
        } else {
            cp_wait<0>();
        }
        __syncthreads();

        #pragma unroll
        for (int kk = 0; kk < BK; kk += 16) {
            const int rA0 = wm * 16 + g;
            unsigned ah[4], al[4];
            ah[0] = *(const unsigned*)&sAhi[sb][rA0    ][kk + t2];
            ah[1] = *(const unsigned*)&sAhi[sb][rA0 + 8][kk + t2];
            ah[2] = *(const unsigned*)&sAhi[sb][rA0    ][kk + t2 + 8];
            ah[3] = *(const unsigned*)&sAhi[sb][rA0 + 8][kk + t2 + 8];
            al[0] = *(const unsigned*)&sAlo[sb][rA0    ][kk + t2];
            al[1] = *(const unsigned*)&sAlo[sb][rA0 + 8][kk + t2];
            al[2] = *(const unsigned*)&sAlo[sb][rA0    ][kk + t2 + 8];
            al[3] = *(const unsigned*)&sAlo[sb][rA0 + 8][kk + t2 + 8];

            #pragma unroll
            for (int nt = 0; nt < 4; nt++) {
                const int nb = wn * 32 + nt * 8 + g;
                unsigned bh0 = *(const unsigned*)&sBhi[sb][nb][kk + t2];
                unsigned bh1 = *(const unsigned*)&sBhi[sb][nb][kk + t2 + 8];
                unsigned bl0 = *(const unsigned*)&sBlo[sb][nb][kk + t2];
                unsigned bl1 = *(const unsigned*)&sBlo[sb][nb][kk + t2 + 8];

                asm volatile(
                    "mma.sync.aligned.m16n8k16.row.col.f32.bf16.bf16.f32 "
                    "{%0,%1,%2,%3}, {%4,%5,%6,%7}, {%8,%9}, {%0,%1,%2,%3};"
                    : "+f"(c[nt][0]), "+f"(c[nt][1]), "+f"(c[nt][2]), "+f"(c[nt][3])
                    : "r"(ah[0]), "r"(ah[1]), "r"(ah[2]), "r"(ah[3]), "r"(bh0), "r"(bh1));
                asm volatile(
                    "mma.sync.aligned.m16n8k16.row.col.f32.bf16.bf16.f32 "
                    "{%0,%1,%2,%3}, {%4,%5,%6,%7}, {%8,%9}, {%0,%1,%2,%3};"
                    : "+f"(c[nt][0]), "+f"(c[nt][1]), "+f"(c[nt][2]), "+f"(c[nt][3])
                    : "r"(ah[0]), "r"(ah[1]), "r"(ah[2]), "r"(ah[3]), "r"(bl0), "r"(bl1));
                asm volatile(
                    "mma.sync.aligned.m16n8k16.row.col.f32.bf16.bf16.f32 "
                    "{%0,%1,%2,%3}, {%4,%5,%6,%7}, {%8,%9}, {%0,%1,%2,%3};"
                    : "+f"(c[nt][0]), "+f"(c[nt][1]), "+f"(c[nt][2]), "+f"(c[nt][3])
                    : "r"(al[0]), "r"(al[1]), "r"(al[2]), "r"(al[3]), "r"(bh0), "r"(bh1));
            }
        }
        __syncthreads();
    }

    // ---- epilogue: z = c + xp; h = tanh(z); write bf16 hi/lo split
    #pragma unroll
    for (int nt = 0; nt < 4; nt++) {
        const int n_e = n0 + wn * 32 + nt * 8 + t2;
        #pragma unroll
        for (int r = 0; r < 2; r++) {
            const int m_e = m0 + wm * 16 + g + r * 8;
            float2 xv = *reinterpret_cast<const float2*>(&xp[(size_t)m_e * HID + n_e]);
            float h0 = tanhf(c[nt][r * 2 + 0] + xv.x);
            float h1 = tanhf(c[nt][r * 2 + 1] + xv.y);
            __nv_bfloat16 hi0 = __float2bfloat16(h0);
            __nv_bfloat16 hi1 = __float2bfloat16(h1);
            __nv_bfloat16 lo0 = __float2bfloat16(h0 - __bfloat162float(hi0));
            __nv_bfloat16 lo1 = __float2bfloat16(h1 - __bfloat162float(hi1));
            __nv_bfloat162 vh; vh.x = hi0; vh.y = hi1;
            __nv_bfloat162 vl; vl.x = lo0; vl.y = lo1;
            *reinterpret_cast<__nv_bfloat162*>(&Ahi_w[(size_t)m_e * HID + n_e]) = vh;
            *reinterpret_cast<__nv_bfloat162*>(&Alo_w[(size_t)m_e * HID + n_e]) = vl;
        }
    }
}

// ---------------------------------------------------------------------------
// Output: logits = h_final @ Why + bo; softmax. One warp per batch row.
// ---------------------------------------------------------------------------
__global__ void out_kernel(const float* __restrict__ Why,
                           const float* __restrict__ bo,
                           float* __restrict__ out)
{
    const int b    = blockIdx.x;
    const int lane = threadIdx.x;
    const __nv_bfloat16* __restrict__ hh = g_Ahi[(SEQ - 1) & 1];
    const __nv_bfloat16* __restrict__ hl = g_Alo[(SEQ - 1) & 1];

    float acc[NOUT] = {};
    for (int k = lane; k < HID; k += 32) {
        float hv = __bfloat162float(hh[(size_t)b * HID + k]) +
                   __bfloat162float(hl[(size_t)b * HID + k]);
        #pragma unroll
        for (int o = 0; o < NOUT; o++)
            acc[o] += hv * Why[k * NOUT + o];
    }
    #pragma unroll
    for (int o = 0; o < NOUT; o++) {
        #pragma unroll
        for (int s = 16; s; s >>= 1)
            acc[o] += __shfl_xor_sync(0xffffffffu, acc[o], s);
        acc[o] += bo[o];
    }
    if (lane == 0) {
        float mx = acc[0];
        #pragma unroll
        for (int o = 1; o < NOUT; o++) mx = fmaxf(mx, acc[o]);
        float sum = 0.f;
        float e[NOUT];
        #pragma unroll
        for (int o = 0; o < NOUT; o++) { e[o] = expf(acc[o] - mx); sum += e[o]; }
        float inv = 1.0f / sum;
        #pragma unroll
        for (int o = 0; o < NOUT; o++) out[b * NOUT + o] = e[o] * inv;
    }
}

// ---------------------------------------------------------------------------
extern "C" void kernel_launch(void* const* d_in, const int* in_sizes, int n_in,
                              void* d_out, int out_size)
{
    const float* x   = (const float*)d_in[0];
    const float* Whx = (const float*)d_in[1];
    const float* Whh = (const float*)d_in[2];
    const float* bh  = (const float*)d_in[3];
    const float* Why = (const float*)d_in[4];
    const float* bo  = (const float*)d_in[5];
    float* out = (float*)d_out;

    dim3 gs(HID / 32, HID / 32);
    split_whh_kernel<<<gs, dim3(32, 8)>>>(Whh);

    dim3 g1(HID / 64, (BATCH * SEQ) / 64);
    xproj_kernel<<<g1, 256>>>(x, Whx, bh);

    step0_kernel<<<(BATCH * HID) / 1024, 1024>>>();

    dim3 g2(HID / 64, BATCH / 32);   // 16 x 8 = 128 CTAs
    for (int t = 1; t < SEQ; t++)
        step_kernel<<<g2, 128>>>(t);

    out_kernel<<<BATCH, 32>>>(Why, bo, out);
}

// round 6
// speedup vs baseline: 1.8975x; 1.0002x over previous
#include <cuda_runtime.h>
#include <cuda_bf16.h>
#include <math.h>

#define BATCH  256
#define SEQ    256
#define IN_DIM 128
#define HID    1024
#define NOUT   10

// ---------------------------------------------------------------------------
// Global scratch
// ---------------------------------------------------------------------------
__device__ float g_xproj[(size_t)SEQ * BATCH * HID];                 // [t][b][h]
__device__ __align__(16) __nv_bfloat16 g_Ahi[2][BATCH * HID];        // h split hi (ping-pong)
__device__ __align__(16) __nv_bfloat16 g_Alo[2][BATCH * HID];        // h split lo
__device__ __align__(16) __nv_bfloat16 g_BThi[HID * HID];            // Whh^T hi: [n][k]
__device__ __align__(16) __nv_bfloat16 g_BTlo[HID * HID];            // Whh^T lo: [n][k]

// ---------------------------------------------------------------------------
// cp.async / ldmatrix helpers
// ---------------------------------------------------------------------------
__device__ __forceinline__ void cp_async16(void* smem_dst, const void* gmem_src) {
    unsigned sa = (unsigned)__cvta_generic_to_shared(smem_dst);
    asm volatile("cp.async.cg.shared.global [%0], [%1], 16;\n" :: "r"(sa), "l"(gmem_src));
}
__device__ __forceinline__ void cp_commit() { asm volatile("cp.async.commit_group;\n"); }
template <int N>
__device__ __forceinline__ void cp_wait() { asm volatile("cp.async.wait_group %0;\n" :: "n"(N)); }

__device__ __forceinline__ void ldsm_x4(unsigned& r0, unsigned& r1, unsigned& r2, unsigned& r3,
                                        const void* p) {
    unsigned a = (unsigned)__cvta_generic_to_shared(p);
    asm volatile("ldmatrix.sync.aligned.m8n8.x4.shared.b16 {%0,%1,%2,%3}, [%4];"
                 : "=r"(r0), "=r"(r1), "=r"(r2), "=r"(r3) : "r"(a));
}

__device__ __forceinline__ void mma_bf16(float* c, const unsigned* a, unsigned b0, unsigned b1) {
    asm volatile(
        "mma.sync.aligned.m16n8k16.row.col.f32.bf16.bf16.f32 "
        "{%0,%1,%2,%3}, {%4,%5,%6,%7}, {%8,%9}, {%0,%1,%2,%3};"
        : "+f"(c[0]), "+f"(c[1]), "+f"(c[2]), "+f"(c[3])
        : "r"(a[0]), "r"(a[1]), "r"(a[2]), "r"(a[3]), "r"(b0), "r"(b1));
}

// ---------------------------------------------------------------------------
// Prep: split Whh (fp32 [k][n]) into transposed bf16 hi/lo [n][k]
// ---------------------------------------------------------------------------
__global__ __launch_bounds__(256) void split_whh_kernel(const float* __restrict__ W)
{
    __shared__ float tile[32][33];
    const int n0 = blockIdx.x * 32;
    const int k0 = blockIdx.y * 32;
    const int tx = threadIdx.x;
    const int ty = threadIdx.y;
    #pragma unroll
    for (int i = 0; i < 4; i++)
        tile[ty + i * 8][tx] = W[(size_t)(k0 + ty + i * 8) * HID + n0 + tx];
    __syncthreads();
    #pragma unroll
    for (int i = 0; i < 4; i++) {
        int n = n0 + ty + i * 8;
        int k = k0 + tx;
        float w = tile[tx][ty + i * 8];
        __nv_bfloat16 hi = __float2bfloat16(w);
        __nv_bfloat16 lo = __float2bfloat16(w - __bfloat162float(hi));
        g_BThi[(size_t)n * HID + k] = hi;
        g_BTlo[(size_t)n * HID + k] = lo;
    }
}

// ---------------------------------------------------------------------------
// Kernel 1: xproj[s][b][h] = x[b][s][:] @ Whx + bh   (fp32 SIMT)
// ---------------------------------------------------------------------------
__global__ __launch_bounds__(256) void xproj_kernel(
    const float* __restrict__ x, const float* __restrict__ Whx,
    const float* __restrict__ bh)
{
    const int n0 = blockIdx.x * 64;
    const int m0 = blockIdx.y * 64;
    __shared__ float As[64][20];
    __shared__ float Bs[16][64];
    const int t  = threadIdx.x;
    const int tx = t & 15;
    const int ty = t >> 4;
    float acc[4][4] = {};

    for (int k0 = 0; k0 < IN_DIM; k0 += 16) {
        {
            int m = t >> 2;
            int k = (t & 3) * 4;
            float4 v = *reinterpret_cast<const float4*>(&x[(size_t)(m0 + m) * IN_DIM + k0 + k]);
            *reinterpret_cast<float4*>(&As[m][k]) = v;
        }
        {
            int k = t >> 4;
            int n = (t & 15) * 4;
            float4 v = *reinterpret_cast<const float4*>(&Whx[(size_t)(k0 + k) * HID + n0 + n]);
            *reinterpret_cast<float4*>(&Bs[k][n]) = v;
        }
        __syncthreads();
        #pragma unroll
        for (int k = 0; k < 16; k++) {
            float a[4];
            #pragma unroll
            for (int i = 0; i < 4; i++) a[i] = As[ty * 4 + i][k];
            float4 bv = *reinterpret_cast<const float4*>(&Bs[k][tx * 4]);
            float b[4] = {bv.x, bv.y, bv.z, bv.w};
            #pragma unroll
            for (int i = 0; i < 4; i++)
                #pragma unroll
                for (int j = 0; j < 4; j++)
                    acc[i][j] += a[i] * b[j];
        }
        __syncthreads();
    }

    float4 bias = *reinterpret_cast<const float4*>(&bh[n0 + tx * 4]);
    #pragma unroll
    for (int i = 0; i < 4; i++) {
        int m  = m0 + ty * 4 + i;
        int b_ = m >> 8;
        int s  = m & 255;
        float4 o;
        o.x = acc[i][0] + bias.x;
        o.y = acc[i][1] + bias.y;
        o.z = acc[i][2] + bias.z;
        o.w = acc[i][3] + bias.w;
        *reinterpret_cast<float4*>(
            &g_xproj[(size_t)s * BATCH * HID + (size_t)b_ * HID + n0 + tx * 4]) = o;
    }
}

// ---------------------------------------------------------------------------
// Step 0: h = tanh(xproj_0), split to bf16 hi/lo in buffer 0
// ---------------------------------------------------------------------------
__global__ void step0_kernel()
{
    int i = blockIdx.x * blockDim.x + threadIdx.x;
    float h = tanhf(g_xproj[i]);
    __nv_bfloat16 hi = __float2bfloat16(h);
    __nv_bfloat16 lo = __float2bfloat16(h - __bfloat162float(hi));
    g_Ahi[0][i] = hi;
    g_Alo[0][i] = lo;
}

// ---------------------------------------------------------------------------
// Step kernel (t >= 1): h_t = tanh(xp_t + h_{t-1} @ Whh)
//   bf16 MMA, 2-term error split, ldmatrix frag loads, split accumulators,
//   3-stage cp.async pipeline. CTA 32x64, 4 warps (2x2 of 16x32). Grid 16x8.
// ---------------------------------------------------------------------------
#define BK   32
#define SA   40           // padded row stride (bf16) -> 80B, LDSM conflict-free
#define NK   (HID / BK)   // 32
#define NSTG 3

__global__ __launch_bounds__(128) void step_kernel(int t)
{
    const __nv_bfloat16* __restrict__ Ahi_r = g_Ahi[(t - 1) & 1];
    const __nv_bfloat16* __restrict__ Alo_r = g_Alo[(t - 1) & 1];
    __nv_bfloat16* __restrict__ Ahi_w = g_Ahi[t & 1];
    __nv_bfloat16* __restrict__ Alo_w = g_Alo[t & 1];
    const float* __restrict__ xp = &g_xproj[(size_t)t * BATCH * HID];

    const int n0 = blockIdx.x * 64;
    const int m0 = blockIdx.y * 32;

    __shared__ __align__(16) __nv_bfloat16 sAhi[NSTG][32][SA];
    __shared__ __align__(16) __nv_bfloat16 sAlo[NSTG][32][SA];
    __shared__ __align__(16) __nv_bfloat16 sBhi[NSTG][64][SA];
    __shared__ __align__(16) __nv_bfloat16 sBlo[NSTG][64][SA];

    const int tid  = threadIdx.x;
    const int lane = tid & 31;
    const int wid  = tid >> 5;
    const int wm   = wid & 1;          // warp M group (16 rows)
    const int wn   = wid >> 1;         // warp N group (32 cols)
    const int g    = lane >> 2;
    const int t2   = (lane & 3) * 2;

    // staging indices
    const int am = tid >> 2;           // 0..31
    const int ch = tid & 3;            // 0..3 (16B chunk)

    // ldmatrix per-lane source rows/cols
    const int lt  = lane >> 3;         // tile index 0..3
    const int lr  = lane & 7;          // row within tile
    // A x4 tiles: {m+r, k} {m+8+r, k} {m+r, k+8} {m+8+r, k+8}
    const int a_row = wm * 16 + (lt & 1) * 8 + lr;
    const int a_col = (lt >> 1) * 8;
    // B x4 tiles (pair of 8-col n tiles): {n+r,k} {n+r,k+8} {n+8+r,k} {n+8+r,k+8}
    const int b_row = (lt >> 1) * 8 + lr;
    const int b_col = (lt & 1) * 8;

    float c1[4][4], c2[4][4], c3[4][4];
    #pragma unroll
    for (int i = 0; i < 4; i++)
        #pragma unroll
        for (int j = 0; j < 4; j++) { c1[i][j] = 0.f; c2[i][j] = 0.f; c3[i][j] = 0.f; }

    auto stage = [&](int kt, int buf) {
        const int k0 = kt * BK;
        cp_async16(&sAhi[buf][am][ch * 8], &Ahi_r[(size_t)(m0 + am) * HID + k0 + ch * 8]);
        cp_async16(&sAlo[buf][am][ch * 8], &Alo_r[(size_t)(m0 + am) * HID + k0 + ch * 8]);
        #pragma unroll
        for (int i = 0; i < 2; i++) {
            int bn = (tid + i * 128) >> 2;
            cp_async16(&sBhi[buf][bn][ch * 8], &g_BThi[(size_t)(n0 + bn) * HID + k0 + ch * 8]);
            cp_async16(&sBlo[buf][bn][ch * 8], &g_BTlo[(size_t)(n0 + bn) * HID + k0 + ch * 8]);
        }
    };

    // prologue: stages 0 and 1
    stage(0, 0); cp_commit();
    stage(1, 1); cp_commit();

    #pragma unroll 3
    for (int kt = 0; kt < NK; kt++) {
        const int sb = kt % NSTG;
        if (kt + 2 < NK) stage(kt + 2, (kt + 2) % NSTG);
        cp_commit();               // commit (possibly empty) to keep group count uniform
        cp_wait<2>();              // stage kt resident
        __syncthreads();

        #pragma unroll
        for (int kk = 0; kk < BK; kk += 16) {
            unsigned ah[4], al[4];
            ldsm_x4(ah[0], ah[1], ah[2], ah[3], &sAhi[sb][a_row][kk + a_col]);
            ldsm_x4(al[0], al[1], al[2], al[3], &sAlo[sb][a_row][kk + a_col]);

            unsigned bh[8], bl[8];   // [nt*2], [nt*2+1] for nt = 0..3
            #pragma unroll
            for (int p = 0; p < 2; p++) {
                const int nb = wn * 32 + p * 16 + b_row;
                ldsm_x4(bh[p * 4 + 0], bh[p * 4 + 1], bh[p * 4 + 2], bh[p * 4 + 3],
                        &sBhi[sb][nb][kk + b_col]);
                ldsm_x4(bl[p * 4 + 0], bl[p * 4 + 1], bl[p * 4 + 2], bl[p * 4 + 3],
                        &sBlo[sb][nb][kk + b_col]);
            }

            #pragma unroll
            for (int nt = 0; nt < 4; nt++) {
                mma_bf16(c1[nt], ah, bh[nt * 2], bh[nt * 2 + 1]);
                mma_bf16(c2[nt], ah, bl[nt * 2], bl[nt * 2 + 1]);
                mma_bf16(c3[nt], al, bh[nt * 2], bh[nt * 2 + 1]);
            }
        }
        __syncthreads();
    }

    // epilogue: h = tanh(c1+c2+c3 + xp); write bf16 hi/lo split
    #pragma unroll
    for (int nt = 0; nt < 4; nt++) {
        const int n_e = n0 + wn * 32 + nt * 8 + t2;
        #pragma unroll
        for (int r = 0; r < 2; r++) {
            const int m_e = m0 + wm * 16 + g + r * 8;
            float2 xv = *reinterpret_cast<const float2*>(&xp[(size_t)m_e * HID + n_e]);
            float z0 = c1[nt][r * 2 + 0] + c2[nt][r * 2 + 0] + c3[nt][r * 2 + 0] + xv.x;
            float z1 = c1[nt][r * 2 + 1] + c2[nt][r * 2 + 1] + c3[nt][r * 2 + 1] + xv.y;
            float h0 = tanhf(z0);
            float h1 = tanhf(z1);
            __nv_bfloat16 hi0 = __float2bfloat16(h0);
            __nv_bfloat16 hi1 = __float2bfloat16(h1);
            __nv_bfloat16 lo0 = __float2bfloat16(h0 - __bfloat162float(hi0));
            __nv_bfloat16 lo1 = __float2bfloat16(h1 - __bfloat162float(hi1));
            __nv_bfloat162 vh; vh.x = hi0; vh.y = hi1;
            __nv_bfloat162 vl; vl.x = lo0; vl.y = lo1;
            *reinterpret_cast<__nv_bfloat162*>(&Ahi_w[(size_t)m_e * HID + n_e]) = vh;
            *reinterpret_cast<__nv_bfloat162*>(&Alo_w[(size_t)m_e * HID + n_e]) = vl;
        }
    }
}

// ---------------------------------------------------------------------------
// Output: logits = h_final @ Why + bo; softmax. One warp per batch row.
// ---------------------------------------------------------------------------
__global__ void out_kernel(const float* __restrict__ Why,
                           const float* __restrict__ bo,
                           float* __restrict__ out)
{
    const int b    = blockIdx.x;
    const int lane = threadIdx.x;
    const __nv_bfloat16* __restrict__ hh = g_Ahi[(SEQ - 1) & 1];
    const __nv_bfloat16* __restrict__ hl = g_Alo[(SEQ - 1) & 1];

    float acc[NOUT] = {};
    for (int k = lane; k < HID; k += 32) {
        float hv = __bfloat162float(hh[(size_t)b * HID + k]) +
                   __bfloat162float(hl[(size_t)b * HID + k]);
        #pragma unroll
        for (int o = 0; o < NOUT; o++)
            acc[o] += hv * Why[k * NOUT + o];
    }
    #pragma unroll
    for (int o = 0; o < NOUT; o++) {
        #pragma unroll
        for (int s = 16; s; s >>= 1)
            acc[o] += __shfl_xor_sync(0xffffffffu, acc[o], s);
        acc[o] += bo[o];
    }
    if (lane == 0) {
        float mx = acc[0];
        #pragma unroll
        for (int o = 1; o < NOUT; o++) mx = fmaxf(mx, acc[o]);
        float sum = 0.f;
        float e[NOUT];
        #pragma unroll
        for (int o = 0; o < NOUT; o++) { e[o] = expf(acc[o] - mx); sum += e[o]; }
        float inv = 1.0f / sum;
        #pragma unroll
        for (int o = 0; o < NOUT; o++) out[b * NOUT + o] = e[o] * inv;
    }
}

// ---------------------------------------------------------------------------
extern "C" void kernel_launch(void* const* d_in, const int* in_sizes, int n_in,
                              void* d_out, int out_size)
{
    const float* x   = (const float*)d_in[0];
    const float* Whx = (const float*)d_in[1];
    const float* Whh = (const float*)d_in[2];
    const float* bh  = (const float*)d_in[3];
    const float* Why = (const float*)d_in[4];
    const float* bo  = (const float*)d_in[5];
    float* out = (float*)d_out;

    dim3 gs(HID / 32, HID / 32);
    split_whh_kernel<<<gs, dim3(32, 8)>>>(Whh);

    dim3 g1(HID / 64, (BATCH * SEQ) / 64);
    xproj_kernel<<<g1, 256>>>(x, Whx, bh);

    step0_kernel<<<(BATCH * HID) / 1024, 1024>>>();

    dim3 g2(HID / 64, BATCH / 32);   // 16 x 8 = 128 CTAs
    for (int t = 1; t < SEQ; t++)
        step_kernel<<<g2, 128>>>(t);

    out_kernel<<<BATCH, 32>>>(Why, bo, out);
}

// round 7
// speedup vs baseline: 3.1596x; 1.6651x over previous
#include <cuda_runtime.h>
#include <cuda_bf16.h>
#include <math.h>

#define BATCH  256
#define SEQ    256
#define IN_DIM 128
#define HID    1024
#define NOUT   10
#define MROWS  (BATCH * SEQ)

// ---------------------------------------------------------------------------
// Global scratch
// ---------------------------------------------------------------------------
__device__ float g_xproj[(size_t)SEQ * BATCH * HID];                  // [s][b][h] fp32
__device__ __align__(16) __nv_bfloat16 g_Ahi[2][BATCH * HID];         // h hi (ping-pong)
__device__ __align__(16) __nv_bfloat16 g_Alo[2][BATCH * HID];         // h lo
__device__ __align__(16) __nv_bfloat16 g_BThi[HID * HID];             // Whh^T hi [n][k]
__device__ __align__(16) __nv_bfloat16 g_BTlo[HID * HID];             // Whh^T lo [n][k]
__device__ __align__(16) __nv_bfloat16 g_BXhi[HID * IN_DIM];          // Whx^T hi [n][k]
__device__ __align__(16) __nv_bfloat16 g_BXlo[HID * IN_DIM];          // Whx^T lo [n][k]
__device__ __align__(16) __nv_bfloat16 g_Xhi[(size_t)MROWS * IN_DIM]; // x hi [m][k]
__device__ __align__(16) __nv_bfloat16 g_Xlo[(size_t)MROWS * IN_DIM]; // x lo
__device__ unsigned g_bar[8];                                         // group barriers

// ---------------------------------------------------------------------------
// helpers
// ---------------------------------------------------------------------------
__device__ __forceinline__ void cp_async16(void* smem_dst, const void* gmem_src) {
    unsigned sa = (unsigned)__cvta_generic_to_shared(smem_dst);
    asm volatile("cp.async.cg.shared.global [%0], [%1], 16;\n" :: "r"(sa), "l"(gmem_src));
}
__device__ __forceinline__ void cp_commit() { asm volatile("cp.async.commit_group;\n"); }
template <int N>
__device__ __forceinline__ void cp_wait() { asm volatile("cp.async.wait_group %0;\n" :: "n"(N)); }

__device__ __forceinline__ void ldsm_x4(unsigned& r0, unsigned& r1, unsigned& r2, unsigned& r3,
                                        const void* p) {
    unsigned a = (unsigned)__cvta_generic_to_shared(p);
    asm volatile("ldmatrix.sync.aligned.m8n8.x4.shared.b16 {%0,%1,%2,%3}, [%4];"
                 : "=r"(r0), "=r"(r1), "=r"(r2), "=r"(r3) : "r"(a));
}
__device__ __forceinline__ void mma_bf16(float* c, const unsigned* a, unsigned b0, unsigned b1) {
    asm volatile(
        "mma.sync.aligned.m16n8k16.row.col.f32.bf16.bf16.f32 "
        "{%0,%1,%2,%3}, {%4,%5,%6,%7}, {%8,%9}, {%0,%1,%2,%3};"
        : "+f"(c[0]), "+f"(c[1]), "+f"(c[2]), "+f"(c[3])
        : "r"(a[0]), "r"(a[1]), "r"(a[2]), "r"(a[3]), "r"(b0), "r"(b1));
}
__device__ __forceinline__ void split2(float v, __nv_bfloat16& hi, __nv_bfloat16& lo) {
    hi = __float2bfloat16(v);
    lo = __float2bfloat16(v - __bfloat162float(hi));
}

// ---------------------------------------------------------------------------
// Prep kernels: weight splits (transposed), x split
// ---------------------------------------------------------------------------
__global__ __launch_bounds__(256) void split_whh_kernel(const float* __restrict__ W)
{
    __shared__ float tile[32][33];
    const int n0 = blockIdx.x * 32, k0 = blockIdx.y * 32;
    const int tx = threadIdx.x, ty = threadIdx.y;
    #pragma unroll
    for (int i = 0; i < 4; i++)
        tile[ty + i * 8][tx] = W[(size_t)(k0 + ty + i * 8) * HID + n0 + tx];
    __syncthreads();
    #pragma unroll
    for (int i = 0; i < 4; i++) {
        int n = n0 + ty + i * 8, k = k0 + tx;
        __nv_bfloat16 hi, lo; split2(tile[tx][ty + i * 8], hi, lo);
        g_BThi[(size_t)n * HID + k] = hi;
        g_BTlo[(size_t)n * HID + k] = lo;
    }
}

__global__ __launch_bounds__(256) void split_whx_kernel(const float* __restrict__ W)
{
    __shared__ float tile[32][33];
    const int n0 = blockIdx.x * 32, k0 = blockIdx.y * 32;
    const int tx = threadIdx.x, ty = threadIdx.y;
    #pragma unroll
    for (int i = 0; i < 4; i++)
        tile[ty + i * 8][tx] = W[(size_t)(k0 + ty + i * 8) * HID + n0 + tx];
    __syncthreads();
    #pragma unroll
    for (int i = 0; i < 4; i++) {
        int n = n0 + ty + i * 8, k = k0 + tx;
        __nv_bfloat16 hi, lo; split2(tile[tx][ty + i * 8], hi, lo);
        g_BXhi[(size_t)n * IN_DIM + k] = hi;
        g_BXlo[(size_t)n * IN_DIM + k] = lo;
    }
}

__global__ __launch_bounds__(256) void xsplit_kernel(const float* __restrict__ x)
{
    size_t i = ((size_t)blockIdx.x * 256 + threadIdx.x) * 4;
    float4 v = *reinterpret_cast<const float4*>(&x[i]);
    __nv_bfloat16 h0,h1,h2,h3,l0,l1,l2,l3;
    split2(v.x,h0,l0); split2(v.y,h1,l1); split2(v.z,h2,l2); split2(v.w,h3,l3);
    __nv_bfloat162 a,b,c,d;
    a.x=h0; a.y=h1; b.x=h2; b.y=h3; c.x=l0; c.y=l1; d.x=l2; d.y=l3;
    *reinterpret_cast<__nv_bfloat162*>(&g_Xhi[i])     = a;
    *reinterpret_cast<__nv_bfloat162*>(&g_Xhi[i + 2]) = b;
    *reinterpret_cast<__nv_bfloat162*>(&g_Xlo[i])     = c;
    *reinterpret_cast<__nv_bfloat162*>(&g_Xlo[i + 2]) = d;
}

// ---------------------------------------------------------------------------
// xproj via bf16 MMA (3-term split): M=65536, N=1024, K=128.
// CTA 64x256, 256 thr (8 warps = 2M x 4N, warp 32x64). Full K in smem.
// ---------------------------------------------------------------------------
#define XP_SMEM ((2 * 64 * 136 + 2 * 256 * 136) * 2)

__global__ __launch_bounds__(256) void xproj_mma_kernel(const float* __restrict__ bh)
{
    extern __shared__ __align__(16) char sm_raw[];
    __nv_bfloat16* sAh = (__nv_bfloat16*)sm_raw;     // [64][136]
    __nv_bfloat16* sAl = sAh + 64 * 136;
    __nv_bfloat16* sBh = sAl + 64 * 136;             // [256][136]
    __nv_bfloat16* sBl = sBh + 256 * 136;

    const int m0 = blockIdx.y * 64;
    const int n0 = blockIdx.x * 256;
    const int tid = threadIdx.x, lane = tid & 31, wid = tid >> 5;
    const int wm = wid >> 2, wn = wid & 3;
    const int lt = lane >> 3, lr = lane & 7;
    const int g = lane >> 2, t2 = (lane & 3) * 2;
    const int a_sub = (lt & 1) * 8 + lr, a_cs = (lt >> 1) * 8;
    const int b_sub = (lt >> 1) * 8 + lr, b_cs = (lt & 1) * 8;

    // stage A (64x128 hi/lo) and B (256x128 hi/lo)
    #pragma unroll
    for (int i = 0; i < 4; i++) {
        int p = tid + i * 256, r = p >> 4, c = p & 15;
        cp_async16(&sAh[r * 136 + c * 8], &g_Xhi[(size_t)(m0 + r) * IN_DIM + c * 8]);
        cp_async16(&sAl[r * 136 + c * 8], &g_Xlo[(size_t)(m0 + r) * IN_DIM + c * 8]);
    }
    #pragma unroll
    for (int i = 0; i < 16; i++) {
        int p = tid + i * 256, r = p >> 4, c = p & 15;
        cp_async16(&sBh[r * 136 + c * 8], &g_BXhi[(size_t)(n0 + r) * IN_DIM + c * 8]);
        cp_async16(&sBl[r * 136 + c * 8], &g_BXlo[(size_t)(n0 + r) * IN_DIM + c * 8]);
    }
    cp_commit(); cp_wait<0>(); __syncthreads();

    float c_[2][8][4];
    #pragma unroll
    for (int i = 0; i < 2; i++)
        #pragma unroll
        for (int j = 0; j < 8; j++)
            #pragma unroll
            for (int q = 0; q < 4; q++) c_[i][j][q] = 0.f;

    #pragma unroll
    for (int kk = 0; kk < IN_DIM; kk += 16) {
        unsigned ah2[2][4], al2[2][4], bhf[4][4], blf[4][4];
        #pragma unroll
        for (int mt = 0; mt < 2; mt++) {
            int row = wm * 32 + mt * 16 + a_sub;
            ldsm_x4(ah2[mt][0], ah2[mt][1], ah2[mt][2], ah2[mt][3], &sAh[row * 136 + kk + a_cs]);
            ldsm_x4(al2[mt][0], al2[mt][1], al2[mt][2], al2[mt][3], &sAl[row * 136 + kk + a_cs]);
        }
        #pragma unroll
        for (int p = 0; p < 4; p++) {
            int row = wn * 64 + p * 16 + b_sub;
            ldsm_x4(bhf[p][0], bhf[p][1], bhf[p][2], bhf[p][3], &sBh[row * 136 + kk + b_cs]);
            ldsm_x4(blf[p][0], blf[p][1], blf[p][2], blf[p][3], &sBl[row * 136 + kk + b_cs]);
        }
        #pragma unroll
        for (int mt = 0; mt < 2; mt++)
            #pragma unroll
            for (int nt = 0; nt < 8; nt++) {
                int p = nt >> 1, q = (nt & 1) * 2;
                mma_bf16(c_[mt][nt], ah2[mt], bhf[p][q], bhf[p][q + 1]);
                mma_bf16(c_[mt][nt], ah2[mt], blf[p][q], blf[p][q + 1]);
                mma_bf16(c_[mt][nt], al2[mt], bhf[p][q], bhf[p][q + 1]);
            }
    }

    #pragma unroll
    for (int mt = 0; mt < 2; mt++)
        #pragma unroll
        for (int nt = 0; nt < 8; nt++) {
            int n_e = n0 + wn * 64 + nt * 8 + t2;
            float2 bb = *reinterpret_cast<const float2*>(&bh[n_e]);
            #pragma unroll
            for (int rr = 0; rr < 2; rr++) {
                int m_e = m0 + wm * 32 + mt * 16 + g + rr * 8;
                int b_ = m_e >> 8, s = m_e & 255;
                float2 o;
                o.x = c_[mt][nt][rr * 2 + 0] + bb.x;
                o.y = c_[mt][nt][rr * 2 + 1] + bb.y;
                *reinterpret_cast<float2*>(
                    &g_xproj[((size_t)s * BATCH + b_) * HID + n_e]) = o;
            }
        }
}

// ---------------------------------------------------------------------------
// Step 0: h = tanh(xproj_0) -> buf 0; also reset group barriers.
// ---------------------------------------------------------------------------
__global__ void step0_kernel()
{
    if (blockIdx.x == 0 && threadIdx.x < 8) g_bar[threadIdx.x] = 0;
    int i = blockIdx.x * blockDim.x + threadIdx.x;
    float h = tanhf(g_xproj[i]);
    __nv_bfloat16 hi, lo; split2(h, hi, lo);
    g_Ahi[0][i] = hi;
    g_Alo[0][i] = lo;
}

// ---------------------------------------------------------------------------
// Persistent RNN kernel: all steps t=1..255 in one launch.
// 128 CTAs (mg 0..7 x ng 0..15), tile 32(M) x 64(N), 256 thr (2M x 4N warps,
// warp tile 16x16). Whh^T hi slice (64x1024) persistent in smem; Whh^T lo and
// A(hi/lo) streamed per 128-wide K chunk with double-buffered cp.async.
// Group-of-16 global barrier per M-tile per step.
// ---------------------------------------------------------------------------
#define P_BPER  (64 * 1032)
#define P_BLO   (64 * 136)
#define P_A     (32 * 136)
#define P_SMEM  ((P_BPER + 2 * P_BLO + 4 * P_A) * 2)

__global__ __launch_bounds__(256) void rnn_persist_kernel()
{
    extern __shared__ __align__(16) char sm_raw[];
    __nv_bfloat16* sBper = (__nv_bfloat16*)sm_raw;       // [64][1032] persistent Whh^T hi
    __nv_bfloat16* sBlo  = sBper + P_BPER;               // [2][64][136]
    __nv_bfloat16* sAh   = sBlo + 2 * P_BLO;             // [2][32][136]
    __nv_bfloat16* sAl   = sAh + 2 * P_A;                // [2][32][136]

    const int bx = blockIdx.x;
    const int ng = bx >> 3, mg = bx & 7;
    const int n0 = ng * 64, m0 = mg * 32;

    const int tid = threadIdx.x, lane = tid & 31, wid = tid >> 5;
    const int wm = wid >> 2, wn = wid & 3;
    const int lt = lane >> 3, lr = lane & 7;
    const int g = lane >> 2, t2 = (lane & 3) * 2;
    const int a_row = wm * 16 + (lt & 1) * 8 + lr;
    const int a_cs  = (lt >> 1) * 8;
    const int b_row = wn * 16 + (lt >> 1) * 8 + lr;
    const int b_cs  = (lt & 1) * 8;
    const int m_e0  = m0 + wm * 16 + g;
    const int n_e0  = n0 + wn * 16 + t2;

    // ---- load persistent Whh^T hi slice (64 x 1024)
    #pragma unroll
    for (int i = 0; i < 32; i++) {
        int p = tid + i * 256, r = p >> 7, c = p & 127;
        cp_async16(&sBper[r * 1032 + c * 8], &g_BThi[(size_t)(n0 + r) * HID + c * 8]);
    }
    cp_commit(); cp_wait<0>(); __syncthreads();

    for (int t = 1; t < SEQ; t++) {
        const __nv_bfloat16* __restrict__ Ah_r = g_Ahi[(t - 1) & 1];
        const __nv_bfloat16* __restrict__ Al_r = g_Alo[(t - 1) & 1];
        __nv_bfloat16* __restrict__ Ah_w = g_Ahi[t & 1];
        __nv_bfloat16* __restrict__ Al_w = g_Alo[t & 1];
        const float* __restrict__ xp = &g_xproj[(size_t)t * BATCH * HID];

        // prefetch xp tile into regs (no cross-CTA dependency)
        float2 xv[4];
        #pragma unroll
        for (int rr = 0; rr < 2; rr++)
            #pragma unroll
            for (int nt = 0; nt < 2; nt++)
                xv[rr * 2 + nt] = *reinterpret_cast<const float2*>(
                    &xp[(size_t)(m_e0 + rr * 8) * HID + n_e0 + nt * 8]);

        // wait for step t-1 writers of this M-group
        if (tid == 0) {
            unsigned tgt = 16u * (unsigned)(t - 1), v;
            do {
                asm volatile("ld.acquire.gpu.u32 %0, [%1];" : "=r"(v) : "l"(&g_bar[mg]));
            } while (v < tgt);
        }
        __syncthreads();

        // k-chunk pipeline
        auto stage = [&](int kt, int buf) {
            const int k0 = kt * 128;
            #pragma unroll
            for (int i = 0; i < 2; i++) {
                int p = tid + i * 256, r = p >> 4, c = p & 15;
                cp_async16(&sAh[buf * P_A + r * 136 + c * 8],
                           &Ah_r[(size_t)(m0 + r) * HID + k0 + c * 8]);
                cp_async16(&sAl[buf * P_A + r * 136 + c * 8],
                           &Al_r[(size_t)(m0 + r) * HID + k0 + c * 8]);
            }
            #pragma unroll
            for (int i = 0; i < 4; i++) {
                int p = tid + i * 256, r = p >> 4, c = p & 15;
                cp_async16(&sBlo[buf * P_BLO + r * 136 + c * 8],
                           &g_BTlo[(size_t)(n0 + r) * HID + k0 + c * 8]);
            }
        };

        float c1[2][4], c2[2][4], c3[2][4];
        #pragma unroll
        for (int i = 0; i < 2; i++)
            #pragma unroll
            for (int j = 0; j < 4; j++) { c1[i][j] = 0.f; c2[i][j] = 0.f; c3[i][j] = 0.f; }

        stage(0, 0); cp_commit();

        for (int kt = 0; kt < 8; kt++) {
            const int buf = kt & 1;
            if (kt < 7) { stage(kt + 1, (kt + 1) & 1); cp_commit(); cp_wait<1>(); }
            else        { cp_wait<0>(); }
            __syncthreads();

            #pragma unroll
            for (int kk = 0; kk < 128; kk += 16) {
                unsigned ah[4], al[4], bh[4], bl[4];
                ldsm_x4(ah[0], ah[1], ah[2], ah[3],
                        &sAh[buf * P_A + a_row * 136 + kk + a_cs]);
                ldsm_x4(al[0], al[1], al[2], al[3],
                        &sAl[buf * P_A + a_row * 136 + kk + a_cs]);
                ldsm_x4(bh[0], bh[1], bh[2], bh[3],
                        &sBper[b_row * 1032 + kt * 128 + kk + b_cs]);
                ldsm_x4(bl[0], bl[1], bl[2], bl[3],
                        &sBlo[buf * P_BLO + b_row * 136 + kk + b_cs]);
                #pragma unroll
                for (int nt = 0; nt < 2; nt++) {
                    mma_bf16(c1[nt], ah, bh[nt * 2], bh[nt * 2 + 1]);
                    mma_bf16(c2[nt], ah, bl[nt * 2], bl[nt * 2 + 1]);
                    mma_bf16(c3[nt], al, bh[nt * 2], bh[nt * 2 + 1]);
                }
            }
            __syncthreads();
        }

        // epilogue: tanh(c + xp), split, store
        #pragma unroll
        for (int nt = 0; nt < 2; nt++)
            #pragma unroll
            for (int rr = 0; rr < 2; rr++) {
                float2 x2 = xv[rr * 2 + nt];
                float z0 = c1[nt][rr * 2 + 0] + c2[nt][rr * 2 + 0] + c3[nt][rr * 2 + 0] + x2.x;
                float z1 = c1[nt][rr * 2 + 1] + c2[nt][rr * 2 + 1] + c3[nt][rr * 2 + 1] + x2.y;
                float h0 = tanhf(z0), h1 = tanhf(z1);
                __nv_bfloat16 hi0, lo0, hi1, lo1;
                split2(h0, hi0, lo0); split2(h1, hi1, lo1);
                __nv_bfloat162 vh; vh.x = hi0; vh.y = hi1;
                __nv_bfloat162 vl; vl.x = lo0; vl.y = lo1;
                size_t off = (size_t)(m_e0 + rr * 8) * HID + n_e0 + nt * 8;
                *reinterpret_cast<__nv_bfloat162*>(&Ah_w[off]) = vh;
                *reinterpret_cast<__nv_bfloat162*>(&Al_w[off]) = vl;
            }

        __syncthreads();
        if (tid == 0)
            asm volatile("red.release.gpu.add.u32 [%0], %1;" :: "l"(&g_bar[mg]), "r"(1u));
    }
}

// ---------------------------------------------------------------------------
// Output: logits = h_final @ Why + bo; softmax. One warp per batch row.
// ---------------------------------------------------------------------------
__global__ void out_kernel(const float* __restrict__ Why,
                           const float* __restrict__ bo,
                           float* __restrict__ out)
{
    const int b = blockIdx.x, lane = threadIdx.x;
    const __nv_bfloat16* __restrict__ hh = g_Ahi[(SEQ - 1) & 1];
    const __nv_bfloat16* __restrict__ hl = g_Alo[(SEQ - 1) & 1];

    float acc[NOUT] = {};
    for (int k = lane; k < HID; k += 32) {
        float hv = __bfloat162float(hh[(size_t)b * HID + k]) +
                   __bfloat162float(hl[(size_t)b * HID + k]);
        #pragma unroll
        for (int o = 0; o < NOUT; o++)
            acc[o] += hv * Why[k * NOUT + o];
    }
    #pragma unroll
    for (int o = 0; o < NOUT; o++) {
        #pragma unroll
        for (int s = 16; s; s >>= 1)
            acc[o] += __shfl_xor_sync(0xffffffffu, acc[o], s);
        acc[o] += bo[o];
    }
    if (lane == 0) {
        float mx = acc[0];
        #pragma unroll
        for (int o = 1; o < NOUT; o++) mx = fmaxf(mx, acc[o]);
        float sum = 0.f, e[NOUT];
        #pragma unroll
        for (int o = 0; o < NOUT; o++) { e[o] = expf(acc[o] - mx); sum += e[o]; }
        float inv = 1.0f / sum;
        #pragma unroll
        for (int o = 0; o < NOUT; o++) out[b * NOUT + o] = e[o] * inv;
    }
}

// ---------------------------------------------------------------------------
extern "C" void kernel_launch(void* const* d_in, const int* in_sizes, int n_in,
                              void* d_out, int out_size)
{
    const float* x   = (const float*)d_in[0];
    const float* Whx = (const float*)d_in[1];
    const float* Whh = (const float*)d_in[2];
    const float* bh  = (const float*)d_in[3];
    const float* Why = (const float*)d_in[4];
    const float* bo  = (const float*)d_in[5];
    float* out = (float*)d_out;

    cudaFuncSetAttribute(xproj_mma_kernel,
                         cudaFuncAttributeMaxDynamicSharedMemorySize, XP_SMEM);
    cudaFuncSetAttribute(rnn_persist_kernel,
                         cudaFuncAttributeMaxDynamicSharedMemorySize, P_SMEM);

    split_whh_kernel<<<dim3(HID / 32, HID / 32), dim3(32, 8)>>>(Whh);
    split_whx_kernel<<<dim3(HID / 32, IN_DIM / 32), dim3(32, 8)>>>(Whx);
    xsplit_kernel<<<(MROWS * IN_DIM) / 1024, 256>>>(x);

    xproj_mma_kernel<<<dim3(HID / 256, MROWS / 64), 256, XP_SMEM>>>(bh);

    step0_kernel<<<(BATCH * HID) / 1024, 1024>>>();

    rnn_persist_kernel<<<128, 256, P_SMEM>>>();

    out_kernel<<<BATCH, 32>>>(Why, bo, out);
}

// round 11
// speedup vs baseline: 3.5478x; 1.1229x over previous
#include <cuda_runtime.h>
#include <cuda_bf16.h>
#include <math.h>

#define BATCH  256
#define SEQ    256
#define IN_DIM 128
#define HID    1024
#define NOUT   10
#define MROWS  (BATCH * SEQ)

// ---------------------------------------------------------------------------
// Global scratch
// ---------------------------------------------------------------------------
__device__ float g_xproj[(size_t)SEQ * BATCH * HID];                  // [s][b][h] fp32
__device__ __align__(16) __nv_bfloat16 g_Ahi[2][BATCH * HID];         // h hi (ping-pong)
__device__ __align__(16) __nv_bfloat16 g_Alo[2][BATCH * HID];         // h lo
__device__ __align__(16) __nv_bfloat16 g_BThi[HID * HID];             // Whh^T hi [n][k]
__device__ __align__(16) __nv_bfloat16 g_BTlo[HID * HID];             // Whh^T lo [n][k]
__device__ __align__(16) __nv_bfloat16 g_BXhi[HID * IN_DIM];          // Whx^T hi [n][k]
__device__ __align__(16) __nv_bfloat16 g_BXlo[HID * IN_DIM];          // Whx^T lo [n][k]
__device__ __align__(16) __nv_bfloat16 g_Xhi[(size_t)MROWS * IN_DIM]; // x hi [m][k]
__device__ __align__(16) __nv_bfloat16 g_Xlo[(size_t)MROWS * IN_DIM]; // x lo
__device__ unsigned g_bar[8];                                         // group barriers

// ---------------------------------------------------------------------------
// helpers
// ---------------------------------------------------------------------------
__device__ __forceinline__ void cp_async16(void* smem_dst, const void* gmem_src) {
    unsigned sa = (unsigned)__cvta_generic_to_shared(smem_dst);
    asm volatile("cp.async.cg.shared.global [%0], [%1], 16;\n" :: "r"(sa), "l"(gmem_src));
}
__device__ __forceinline__ void cp_commit() { asm volatile("cp.async.commit_group;\n"); }
template <int N>
__device__ __forceinline__ void cp_wait() { asm volatile("cp.async.wait_group %0;\n" :: "n"(N)); }

__device__ __forceinline__ void ldsm_x4(unsigned& r0, unsigned& r1, unsigned& r2, unsigned& r3,
                                        const void* p) {
    unsigned a = (unsigned)__cvta_generic_to_shared(p);
    asm volatile("ldmatrix.sync.aligned.m8n8.x4.shared.b16 {%0,%1,%2,%3}, [%4];"
                 : "=r"(r0), "=r"(r1), "=r"(r2), "=r"(r3) : "r"(a));
}
__device__ __forceinline__ void mma_bf16(float* c, const unsigned* a, unsigned b0, unsigned b1) {
    asm volatile(
        "mma.sync.aligned.m16n8k16.row.col.f32.bf16.bf16.f32 "
        "{%0,%1,%2,%3}, {%4,%5,%6,%7}, {%8,%9}, {%0,%1,%2,%3};"
        : "+f"(c[0]), "+f"(c[1]), "+f"(c[2]), "+f"(c[3])
        : "r"(a[0]), "r"(a[1]), "r"(a[2]), "r"(a[3]), "r"(b0), "r"(b1));
}
__device__ __forceinline__ void split2(float v, __nv_bfloat16& hi, __nv_bfloat16& lo) {
    hi = __float2bfloat16(v);
    lo = __float2bfloat16(v - __bfloat162float(hi));
}

// ---------------------------------------------------------------------------
// Prep kernels: weight splits (transposed), x split
// ---------------------------------------------------------------------------
__global__ __launch_bounds__(256) void split_whh_kernel(const float* __restrict__ W)
{
    __shared__ float tile[32][33];
    const int n0 = blockIdx.x * 32, k0 = blockIdx.y * 32;
    const int tx = threadIdx.x, ty = threadIdx.y;
    #pragma unroll
    for (int i = 0; i < 4; i++)
        tile[ty + i * 8][tx] = W[(size_t)(k0 + ty + i * 8) * HID + n0 + tx];
    __syncthreads();
    #pragma unroll
    for (int i = 0; i < 4; i++) {
        int n = n0 + ty + i * 8, k = k0 + tx;
        __nv_bfloat16 hi, lo; split2(tile[tx][ty + i * 8], hi, lo);
        g_BThi[(size_t)n * HID + k] = hi;
        g_BTlo[(size_t)n * HID + k] = lo;
    }
}

__global__ __launch_bounds__(256) void split_whx_kernel(const float* __restrict__ W)
{
    __shared__ float tile[32][33];
    const int n0 = blockIdx.x * 32, k0 = blockIdx.y * 32;
    const int tx = threadIdx.x, ty = threadIdx.y;
    #pragma unroll
    for (int i = 0; i < 4; i++)
        tile[ty + i * 8][tx] = W[(size_t)(k0 + ty + i * 8) * HID + n0 + tx];
    __syncthreads();
    #pragma unroll
    for (int i = 0; i < 4; i++) {
        int n = n0 + ty + i * 8, k = k0 + tx;
        __nv_bfloat16 hi, lo; split2(tile[tx][ty + i * 8], hi, lo);
        g_BXhi[(size_t)n * IN_DIM + k] = hi;
        g_BXlo[(size_t)n * IN_DIM + k] = lo;
    }
}

__global__ __launch_bounds__(256) void xsplit_kernel(const float* __restrict__ x)
{
    size_t i = ((size_t)blockIdx.x * 256 + threadIdx.x) * 4;
    float4 v = *reinterpret_cast<const float4*>(&x[i]);
    __nv_bfloat16 h0,h1,h2,h3,l0,l1,l2,l3;
    split2(v.x,h0,l0); split2(v.y,h1,l1); split2(v.z,h2,l2); split2(v.w,h3,l3);
    __nv_bfloat162 a,b,c,d;
    a.x=h0; a.y=h1; b.x=h2; b.y=h3; c.x=l0; c.y=l1; d.x=l2; d.y=l3;
    *reinterpret_cast<__nv_bfloat162*>(&g_Xhi[i])     = a;
    *reinterpret_cast<__nv_bfloat162*>(&g_Xhi[i + 2]) = b;
    *reinterpret_cast<__nv_bfloat162*>(&g_Xlo[i])     = c;
    *reinterpret_cast<__nv_bfloat162*>(&g_Xlo[i + 2]) = d;
}

// ---------------------------------------------------------------------------
// xproj via bf16 MMA (3-term split), B-stationary:
// CTA persists B slice (256N x 128K hi/lo) in smem, loops 4 M-tiles of 64.
// 256 thr = 8 warps (2M x 4N, warp 32x64). Grid (4, 256).
// ---------------------------------------------------------------------------
#define XP_BE   (256 * 136)
#define XP_AE   (64 * 136)
#define XP_SMEM ((2 * XP_BE + 4 * XP_AE) * 2)

__global__ __launch_bounds__(256) void xproj_mma_kernel(const float* __restrict__ bh)
{
    extern __shared__ __align__(16) char sm_raw[];
    __nv_bfloat16* sBh = (__nv_bfloat16*)sm_raw;     // [256][136]
    __nv_bfloat16* sBl = sBh + XP_BE;
    __nv_bfloat16* sAh = sBl + XP_BE;                // [2][64][136]
    __nv_bfloat16* sAl = sAh + 2 * XP_AE;

    const int n0 = blockIdx.x * 256;
    const int mbase = blockIdx.y * 256;
    const int tid = threadIdx.x, lane = tid & 31, wid = tid >> 5;
    const int wm = wid >> 2, wn = wid & 3;
    const int lt = lane >> 3, lr = lane & 7;
    const int g = lane >> 2, t2 = (lane & 3) * 2;
    const int a_sub = (lt & 1) * 8 + lr, a_cs = (lt >> 1) * 8;
    const int b_sub = (lt >> 1) * 8 + lr, b_cs = (lt & 1) * 8;

    auto stageA = [&](int mt, int buf) {
        const int m0 = mbase + mt * 64;
        #pragma unroll
        for (int i = 0; i < 4; i++) {
            int p = tid + i * 256, r = p >> 4, c = p & 15;
            cp_async16(&sAh[buf * XP_AE + r * 136 + c * 8],
                       &g_Xhi[(size_t)(m0 + r) * IN_DIM + c * 8]);
            cp_async16(&sAl[buf * XP_AE + r * 136 + c * 8],
                       &g_Xlo[(size_t)(m0 + r) * IN_DIM + c * 8]);
        }
    };

    // stage B (persistent) + A tile 0
    #pragma unroll
    for (int i = 0; i < 16; i++) {
        int p = tid + i * 256, r = p >> 4, c = p & 15;
        cp_async16(&sBh[r * 136 + c * 8], &g_BXhi[(size_t)(n0 + r) * IN_DIM + c * 8]);
        cp_async16(&sBl[r * 136 + c * 8], &g_BXlo[(size_t)(n0 + r) * IN_DIM + c * 8]);
    }
    stageA(0, 0);
    cp_commit();

    for (int mt = 0; mt < 4; mt++) {
        const int buf = mt & 1;
        if (mt < 3) { stageA(mt + 1, (mt + 1) & 1); cp_commit(); cp_wait<1>(); }
        else        { cp_wait<0>(); }
        __syncthreads();

        float c_[2][8][4];
        #pragma unroll
        for (int i = 0; i < 2; i++)
            #pragma unroll
            for (int j = 0; j < 8; j++)
                #pragma unroll
                for (int q = 0; q < 4; q++) c_[i][j][q] = 0.f;

        #pragma unroll
        for (int kk = 0; kk < IN_DIM; kk += 16) {
            unsigned ah2[2][4], al2[2][4], bhf[4][4], blf[4][4];
            #pragma unroll
            for (int mi = 0; mi < 2; mi++) {
                int row = wm * 32 + mi * 16 + a_sub;
                ldsm_x4(ah2[mi][0], ah2[mi][1], ah2[mi][2], ah2[mi][3],
                        &sAh[buf * XP_AE + row * 136 + kk + a_cs]);
                ldsm_x4(al2[mi][0], al2[mi][1], al2[mi][2], al2[mi][3],
                        &sAl[buf * XP_AE + row * 136 + kk + a_cs]);
            }
            #pragma unroll
            for (int p = 0; p < 4; p++) {
                int row = wn * 64 + p * 16 + b_sub;
                ldsm_x4(bhf[p][0], bhf[p][1], bhf[p][2], bhf[p][3], &sBh[row * 136 + kk + b_cs]);
                ldsm_x4(blf[p][0], blf[p][1], blf[p][2], blf[p][3], &sBl[row * 136 + kk + b_cs]);
            }
            #pragma unroll
            for (int mi = 0; mi < 2; mi++)
                #pragma unroll
                for (int nt = 0; nt < 8; nt++) {
                    int p = nt >> 1, q = (nt & 1) * 2;
                    mma_bf16(c_[mi][nt], ah2[mi], bhf[p][q], bhf[p][q + 1]);
                    mma_bf16(c_[mi][nt], ah2[mi], blf[p][q], blf[p][q + 1]);
                    mma_bf16(c_[mi][nt], al2[mi], bhf[p][q], bhf[p][q + 1]);
                }
        }
        __syncthreads();   // A-buf reads done before next stage overwrites

        const int m0 = mbase + mt * 64;
        #pragma unroll
        for (int mi = 0; mi < 2; mi++)
            #pragma unroll
            for (int nt = 0; nt < 8; nt++) {
                int n_e = n0 + wn * 64 + nt * 8 + t2;
                float2 bb = *reinterpret_cast<const float2*>(&bh[n_e]);
                #pragma unroll
                for (int rr = 0; rr < 2; rr++) {
                    int m_e = m0 + wm * 32 + mi * 16 + g + rr * 8;
                    int b_ = m_e >> 8, s = m_e & 255;
                    float2 o;
                    o.x = c_[mi][nt][rr * 2 + 0] + bb.x;
                    o.y = c_[mi][nt][rr * 2 + 1] + bb.y;
                    *reinterpret_cast<float2*>(
                        &g_xproj[((size_t)s * BATCH + b_) * HID + n_e]) = o;
                }
            }
    }
}

// ---------------------------------------------------------------------------
// Step 0: h = tanh(xproj_0) -> buf 0; also reset group barriers.
// ---------------------------------------------------------------------------
__global__ void step0_kernel()
{
    if (blockIdx.x == 0 && threadIdx.x < 8) g_bar[threadIdx.x] = 0;
    int i = blockIdx.x * blockDim.x + threadIdx.x;
    float h = tanhf(g_xproj[i]);
    __nv_bfloat16 hi, lo; split2(h, hi, lo);
    g_Ahi[0][i] = hi;
    g_Alo[0][i] = lo;
}

// ---------------------------------------------------------------------------
// Persistent RNN kernel: steps t=1..255. 128 CTAs (8 mg x 16 ng), CTA tile
// 32M x 64N, 256 thr. 8 warps = 2M x 2N positions of 16x32 warp tiles with
// 2-way K-split (partner warps sum via smem in epilogue). Whh^T hi slice
// persistent in smem; Whh^T lo + A streamed, Blo pre-staged before barrier.
// ---------------------------------------------------------------------------
#define P_BPER_E (64 * 1032)
#define P_BLO_E  (64 * 136)
#define P_A_E    (32 * 136)
#define P_SMEM   ((P_BPER_E + 2 * P_BLO_E + 4 * P_A_E) * 2 + 4 * 32 * 17 * 4)

__global__ __launch_bounds__(256) void rnn_persist_kernel()
{
    extern __shared__ __align__(16) char sm_raw[];
    __nv_bfloat16* sBper = (__nv_bfloat16*)sm_raw;       // [64][1032]
    __nv_bfloat16* sBlo  = sBper + P_BPER_E;             // [2][64][136]
    __nv_bfloat16* sAh   = sBlo + 2 * P_BLO_E;           // [2][32][136]
    __nv_bfloat16* sAl   = sAh + 2 * P_A_E;              // [2][32][136]
    float*         sRed  = (float*)(sAl + 2 * P_A_E);    // [4][32][17]

    const int bx = blockIdx.x;
    const int ng = bx >> 3, mg = bx & 7;
    const int n0 = ng * 64, m0 = mg * 32;

    const int tid = threadIdx.x, lane = tid & 31, wid = tid >> 5;
    const int wm = wid & 1;            // M position (16 rows)
    const int wn = (wid >> 1) & 1;     // N position (32 cols)
    const int ks = wid >> 2;           // K-split half
    const int pos = wm * 2 + wn;
    const int lt = lane >> 3, lr = lane & 7;
    const int g = lane >> 2, t2 = (lane & 3) * 2;
    const int a_row = wm * 16 + (lt & 1) * 8 + lr;
    const int a_cs  = (lt >> 1) * 8;
    const int b_sub = (lt >> 1) * 8 + lr;
    const int b_cs  = (lt & 1) * 8;
    const int m_e0  = m0 + wm * 16 + g;
    const int n_e0  = n0 + wn * 32 + t2;

    // ---- load persistent Whh^T hi slice (64 x 1024)
    #pragma unroll
    for (int i = 0; i < 32; i++) {
        int p = tid + i * 256, r = p >> 7, c = p & 127;
        cp_async16(&sBper[r * 1032 + c * 8], &g_BThi[(size_t)(n0 + r) * HID + c * 8]);
    }
    cp_commit(); cp_wait<0>(); __syncthreads();

    for (int t = 1; t < SEQ; t++) {
        const __nv_bfloat16* __restrict__ Ah_r = g_Ahi[(t - 1) & 1];
        const __nv_bfloat16* __restrict__ Al_r = g_Alo[(t - 1) & 1];
        __nv_bfloat16* __restrict__ Ah_w = g_Ahi[t & 1];
        __nv_bfloat16* __restrict__ Al_w = g_Alo[t & 1];
        const float* __restrict__ xp = &g_xproj[(size_t)t * BATCH * HID];

        auto stageA = [&](int kt, int buf) {
            const int k0 = kt * 128;
            #pragma unroll
            for (int i = 0; i < 2; i++) {
                int p = tid + i * 256, r = p >> 4, c = p & 15;
                cp_async16(&sAh[buf * P_A_E + r * 136 + c * 8],
                           &Ah_r[(size_t)(m0 + r) * HID + k0 + c * 8]);
                cp_async16(&sAl[buf * P_A_E + r * 136 + c * 8],
                           &Al_r[(size_t)(m0 + r) * HID + k0 + c * 8]);
            }
        };
        auto stageB = [&](int kt, int buf) {
            const int k0 = kt * 128;
            #pragma unroll
            for (int i = 0; i < 4; i++) {
                int p = tid + i * 256, r = p >> 4, c = p & 15;
                cp_async16(&sBlo[buf * P_BLO_E + r * 136 + c * 8],
                           &g_BTlo[(size_t)(n0 + r) * HID + k0 + c * 8]);
            }
        };

        // pre-barrier: xp prefetch (ks==0 only) + Blo chunks 0,1 (h-independent)
        float2 xv[8];
        if (ks == 0) {
            #pragma unroll
            for (int rr = 0; rr < 2; rr++)
                #pragma unroll
                for (int nt = 0; nt < 4; nt++)
                    xv[rr * 4 + nt] = *reinterpret_cast<const float2*>(
                        &xp[(size_t)(m_e0 + rr * 8) * HID + n_e0 + nt * 8]);
        }
        stageB(0, 0);
        stageB(1, 1);
        cp_commit();                               // G1

        // wait for step t-1 writers of this M-group
        if (tid == 0) {
            unsigned tgt = 16u * (unsigned)(t - 1), v;
            do {
                asm volatile("ld.acquire.gpu.u32 %0, [%1];" : "=r"(v) : "l"(&g_bar[mg]));
            } while (v < tgt);
        }
        __syncthreads();

        stageA(0, 0); cp_commit();                 // G2

        float c1[4][4], c2[4][4], c3[4][4];
        #pragma unroll
        for (int i = 0; i < 4; i++)
            #pragma unroll
            for (int j = 0; j < 4; j++) { c1[i][j] = 0.f; c2[i][j] = 0.f; c3[i][j] = 0.f; }

        for (int kt = 0; kt < 8; kt++) {
            const int buf = kt & 1;
            if (kt < 7) {
                stageA(kt + 1, (kt + 1) & 1);
                if (kt + 1 >= 2) stageB(kt + 1, (kt + 1) & 1);
                cp_commit(); cp_wait<1>();
            } else {
                cp_commit(); cp_wait<0>();
            }
            __syncthreads();

            #pragma unroll
            for (int kkj = 0; kkj < 4; kkj++) {
                const int kk = kkj * 32 + ks * 16;
                unsigned ah[4], al[4], bh[8], bl[8];
                ldsm_x4(ah[0], ah[1], ah[2], ah[3],
                        &sAh[buf * P_A_E + a_row * 136 + kk + a_cs]);
                ldsm_x4(al[0], al[1], al[2], al[3],
                        &sAl[buf * P_A_E + a_row * 136 + kk + a_cs]);
                #pragma unroll
                for (int p = 0; p < 2; p++) {
                    const int nb = wn * 32 + p * 16 + b_sub;
                    ldsm_x4(bh[p * 4 + 0], bh[p * 4 + 1], bh[p * 4 + 2], bh[p * 4 + 3],
                            &sBper[nb * 1032 + kt * 128 + kk + b_cs]);
                    ldsm_x4(bl[p * 4 + 0], bl[p * 4 + 1], bl[p * 4 + 2], bl[p * 4 + 3],
                            &sBlo[buf * P_BLO_E + nb * 136 + kk + b_cs]);
                }
                #pragma unroll
                for (int nt = 0; nt < 4; nt++) {
                    const int p = nt >> 1, q = (nt & 1) * 2;
                    mma_bf16(c1[nt], ah, bh[p * 4 + q], bh[p * 4 + q + 1]);
                    mma_bf16(c2[nt], ah, bl[p * 4 + q], bl[p * 4 + q + 1]);
                    mma_bf16(c3[nt], al, bh[p * 4 + q], bh[p * 4 + q + 1]);
                }
            }
            __syncthreads();
        }

        // ---- epilogue: combine K-split halves, tanh, split, store
        float cs[4][4];
        #pragma unroll
        for (int nt = 0; nt < 4; nt++)
            #pragma unroll
            for (int j = 0; j < 4; j++)
                cs[nt][j] = c1[nt][j] + c2[nt][j] + c3[nt][j];

        if (ks == 1) {
            #pragma unroll
            for (int nt = 0; nt < 4; nt++)
                #pragma unroll
                for (int j = 0; j < 4; j++)
                    sRed[(pos * 32 + lane) * 17 + nt * 4 + j] = cs[nt][j];
        }
        __syncthreads();

        if (ks == 0) {
            #pragma unroll
            for (int nt = 0; nt < 4; nt++) {
                #pragma unroll
                for (int rr = 0; rr < 2; rr++) {
                    float p0 = sRed[(pos * 32 + lane) * 17 + nt * 4 + rr * 2 + 0];
                    float p1 = sRed[(pos * 32 + lane) * 17 + nt * 4 + rr * 2 + 1];
                    float2 x2 = xv[rr * 4 + nt];
                    float z0 = cs[nt][rr * 2 + 0] + p0 + x2.x;
                    float z1 = cs[nt][rr * 2 + 1] + p1 + x2.y;
                    float h0 = tanhf(z0), h1 = tanhf(z1);
                    __nv_bfloat16 hi0, lo0, hi1, lo1;
                    split2(h0, hi0, lo0); split2(h1, hi1, lo1);
                    __nv_bfloat162 vh; vh.x = hi0; vh.y = hi1;
                    __nv_bfloat162 vl; vl.x = lo0; vl.y = lo1;
                    size_t off = (size_t)(m_e0 + rr * 8) * HID + n_e0 + nt * 8;
                    *reinterpret_cast<__nv_bfloat162*>(&Ah_w[off]) = vh;
                    *reinterpret_cast<__nv_bfloat162*>(&Al_w[off]) = vl;
                }
            }
        }
        __syncthreads();
        if (tid == 0)
            asm volatile("red.release.gpu.add.u32 [%0], %1;" :: "l"(&g_bar[mg]), "r"(1u));
    }
}

// ---------------------------------------------------------------------------
// Output: logits = h_final @ Why + bo; softmax. One warp per batch row.
// ---------------------------------------------------------------------------
__global__ void out_kernel(const float* __restrict__ Why,
                           const float* __restrict__ bo,
                           float* __restrict__ out)
{
    const int b = blockIdx.x, lane = threadIdx.x;
    const __nv_bfloat16* __restrict__ hh = g_Ahi[(SEQ - 1) & 1];
    const __nv_bfloat16* __restrict__ hl = g_Alo[(SEQ - 1) & 1];

    float acc[NOUT] = {};
    for (int k = lane; k < HID; k += 32) {
        float hv = __bfloat162float(hh[(size_t)b * HID + k]) +
                   __bfloat162float(hl[(size_t)b * HID + k]);
        #pragma unroll
        for (int o = 0; o < NOUT; o++)
            acc[o] += hv * Why[k * NOUT + o];
    }
    #pragma unroll
    for (int o = 0; o < NOUT; o++) {
        #pragma unroll
        for (int s = 16; s; s >>= 1)
            acc[o] += __shfl_xor_sync(0xffffffffu, acc[o], s);
        acc[o] += bo[o];
    }
    if (lane == 0) {
        float mx = acc[0];
        #pragma unroll
        for (int o = 1; o < NOUT; o++) mx = fmaxf(mx, acc[o]);
        float sum = 0.f, e[NOUT];
        #pragma unroll
        for (int o = 0; o < NOUT; o++) { e[o] = expf(acc[o] - mx); sum += e[o]; }
        float inv = 1.0f / sum;
        #pragma unroll
        for (int o = 0; o < NOUT; o++) out[b * NOUT + o] = e[o] * inv;
    }
}

// ---------------------------------------------------------------------------
extern "C" void kernel_launch(void* const* d_in, const int* in_sizes, int n_in,
                              void* d_out, int out_size)
{
    const float* x   = (const float*)d_in[0];
    const float* Whx = (const float*)d_in[1];
    const float* Whh = (const float*)d_in[2];
    const float* bh  = (const float*)d_in[3];
    const float* Why = (const float*)d_in[4];
    const float* bo  = (const float*)d_in[5];
    float* out = (float*)d_out;

    cudaFuncSetAttribute(xproj_mma_kernel,
                         cudaFuncAttributeMaxDynamicSharedMemorySize, XP_SMEM);
    cudaFuncSetAttribute(rnn_persist_kernel,
                         cudaFuncAttributeMaxDynamicSharedMemorySize, P_SMEM);

    split_whh_kernel<<<dim3(HID / 32, HID / 32), dim3(32, 8)>>>(Whh);
    split_whx_kernel<<<dim3(HID / 32, IN_DIM / 32), dim3(32, 8)>>>(Whx);
    xsplit_kernel<<<(MROWS * IN_DIM) / 1024, 256>>>(x);

    xproj_mma_kernel<<<dim3(HID / 256, MROWS / 256), 256, XP_SMEM>>>(bh);

    step0_kernel<<<(BATCH * HID) / 1024, 1024>>>();

    rnn_persist_kernel<<<128, 256, P_SMEM>>>();

    out_kernel<<<BATCH, 32>>>(Why, bo, out);
}